// round 9
// baseline (speedup 1.0000x reference)
#include <cuda_runtime.h>
#include <cstdint>

#define D_DIM 4096
#define TPB   512
#define EPT   8   // elements per thread (512*8 = 4096)

// ---------------- Threefry-2x32 (JAX 20-round schedule), host scalar ----------------

static inline uint32_t rotl_host(uint32_t x, int r) { return (x << r) | (x >> (32 - r)); }

static void tf2x32_host(uint32_t k1, uint32_t k2, uint32_t x0, uint32_t x1,
                        uint32_t& o0, uint32_t& o1) {
    const uint32_t ks2 = k1 ^ k2 ^ 0x1BD11BDAu;
    x0 += k1; x1 += k2;
#define TF_RH(r) { x0 += x1; x1 = rotl_host(x1, (r)); x1 ^= x0; }
    TF_RH(13) TF_RH(15) TF_RH(26) TF_RH(6)   x0 += k2;  x1 += ks2 + 1u;
    TF_RH(17) TF_RH(29) TF_RH(16) TF_RH(24)  x0 += ks2; x1 += k1  + 2u;
    TF_RH(13) TF_RH(15) TF_RH(26) TF_RH(6)   x0 += k1;  x1 += k2  + 3u;
    TF_RH(17) TF_RH(29) TF_RH(16) TF_RH(24)  x0 += k2;  x1 += ks2 + 4u;
    TF_RH(13) TF_RH(15) TF_RH(26) TF_RH(6)   x0 += ks2; x1 += k1  + 5u;
#undef TF_RH
    o0 = x0; o1 = x1;
}

// Device scalar version (used once per block for the randint draw)
__device__ __forceinline__ void tf2x32_dev(uint32_t k1, uint32_t k2,
                                           uint32_t x0, uint32_t x1,
                                           uint32_t& o0, uint32_t& o1) {
    const uint32_t ks2 = k1 ^ k2 ^ 0x1BD11BDAu;
    x0 += k1; x1 += k2;
#define TF_R(r) { x0 += x1; x1 = __funnelshift_l(x1, x1, (r)); x1 ^= x0; }
    TF_R(13) TF_R(15) TF_R(26) TF_R(6)   x0 += k2;  x1 += ks2 + 1u;
    TF_R(17) TF_R(29) TF_R(16) TF_R(24)  x0 += ks2; x1 += k1  + 2u;
    TF_R(13) TF_R(15) TF_R(26) TF_R(6)   x0 += k1;  x1 += k2  + 3u;
    TF_R(17) TF_R(29) TF_R(16) TF_R(24)  x0 += k2;  x1 += ks2 + 4u;
    TF_R(13) TF_R(15) TF_R(26) TF_R(6)   x0 += ks2; x1 += k1  + 5u;
#undef TF_R
    o0 = x0; o1 = x1;
}

// ---------------- Kernel: one CTA per row ----------------

__global__ __launch_bounds__(TPB, 3)
void nade_mask_kernel(const float* __restrict__ x, float* __restrict__ out,
                      uint32_t kp0, uint32_t kp1,   // k_perm  (uniform scores)
                      uint32_t s20, uint32_t s21) { // randint lower-bits key
    __shared__ uint32_t hist[D_DIM];     // count -> (count<<24)|excl_prefix
    __shared__ uint32_t scat[D_DIM];     // composite keys grouped by bucket
    __shared__ float    mskf[D_DIM];     // final per-position mask (fully written in P4)
    __shared__ uint32_t wsum[TPB / 32];
    __shared__ uint32_t s_n;

    const int t = threadIdx.x;
    const uint32_t b = blockIdx.x;

    {   // Phase 0: vectorized zeroing of hist only
        uint4 z = make_uint4(0u, 0u, 0u, 0u);
        uint4* h4 = reinterpret_cast<uint4*>(hist);
#pragma unroll
        for (int k = 0; k < D_DIM / 4 / TPB; k++) h4[k * TPB + t] = z;
    }
    if (t == 0) {
        uint32_t o0, o1;
        tf2x32_dev(s20, s21, 0u, b, o0, o1);
        s_n = (o0 ^ o1) & (D_DIM - 1u);   // span=4096 power of two -> bits & 4095
    }
    __syncthreads();

    // ---- Phase 1: 8 threefry chains interleaved; ONE atomic pass.
    // atomicAdd return = unique within-bucket arrival index p; pack 8x8b into 2 regs.
    uint32_t m_[EPT];
    uint32_t pp0 = 0u, pp1 = 0u;
    {
        uint32_t X0[EPT], X1[EPT];
        const uint32_t ks2 = kp0 ^ kp1 ^ 0x1BD11BDAu;
        const uint32_t fbase = b * (uint32_t)D_DIM + (uint32_t)t * EPT;
#pragma unroll
        for (int e = 0; e < EPT; e++) { X0[e] = kp0; X1[e] = (fbase + (uint32_t)e) + kp1; }
#define R8(r) _Pragma("unroll") \
        for (int e = 0; e < EPT; e++) { X0[e] += X1[e]; \
            X1[e] = __funnelshift_l(X1[e], X1[e], (r)); X1[e] ^= X0[e]; }
#define INJ8(a, bb) _Pragma("unroll") \
        for (int e = 0; e < EPT; e++) { X0[e] += (a); X1[e] += (bb); }
        R8(13) R8(15) R8(26) R8(6)   INJ8(kp1, ks2 + 1u)
        R8(17) R8(29) R8(16) R8(24)  INJ8(ks2, kp0 + 2u)
        R8(13) R8(15) R8(26) R8(6)   INJ8(kp0, kp1 + 3u)
        R8(17) R8(29) R8(16) R8(24)  INJ8(kp1, ks2 + 4u)
        R8(13) R8(15) R8(26) R8(6)   INJ8(ks2, kp0 + 5u)
#undef R8
#undef INJ8
#pragma unroll
        for (int e = 0; e < EPT; e++) {
            uint32_t m = (X0[e] ^ X1[e]) >> 9;   // 23-bit mantissa key
            m_[e] = m;
            uint32_t p = atomicAdd(&hist[m >> 11], 1u);   // arrival index
            if (e < 4) pp0 |= p << (8 * e);
            else       pp1 |= p << (8 * (e - 4));
        }
    }
    __syncthreads();

    // ---- Phase 2: exclusive scan of 4096 bins; pack (count<<24)|excl back into hist
    const int hb = t * EPT;
    uint4 h0 = *reinterpret_cast<uint4*>(&hist[hb]);
    uint4 h1 = *reinterpret_cast<uint4*>(&hist[hb + 4]);
    uint32_t c_[EPT] = {h0.x, h0.y, h0.z, h0.w, h1.x, h1.y, h1.z, h1.w};
    uint32_t loc[EPT], run = 0;
#pragma unroll
    for (int e = 0; e < EPT; e++) { loc[e] = run; run += c_[e]; }
    uint32_t v = run;
    const int lane = t & 31, wid = t >> 5;
#pragma unroll
    for (int d = 1; d < 32; d <<= 1) {
        uint32_t y = __shfl_up_sync(0xFFFFFFFFu, v, d);
        if (lane >= d) v += y;
    }
    if (lane == 31) wsum[wid] = v;
    __syncthreads();
    if (t == 0) {
        uint32_t acc = 0;
#pragma unroll
        for (int i = 0; i < TPB / 32; i++) { uint32_t c = wsum[i]; wsum[i] = acc; acc += c; }
    }
    __syncthreads();
    const uint32_t texcl = wsum[wid] + (v - run);
    h0.x = (c_[0] << 24) | (texcl + loc[0]);
    h0.y = (c_[1] << 24) | (texcl + loc[1]);
    h0.z = (c_[2] << 24) | (texcl + loc[2]);
    h0.w = (c_[3] << 24) | (texcl + loc[3]);
    h1.x = (c_[4] << 24) | (texcl + loc[4]);
    h1.y = (c_[5] << 24) | (texcl + loc[5]);
    h1.z = (c_[6] << 24) | (texcl + loc[6]);
    h1.w = (c_[7] << 24) | (texcl + loc[7]);
    *reinterpret_cast<uint4*>(&hist[hb]) = h0;
    *reinterpret_cast<uint4*>(&hist[hb + 4]) = h1;
    __syncthreads();

    // ---- Phase 3: scatter composite keys into bucket segments (uniform, no branch)
#pragma unroll
    for (int e = 0; e < EPT; e++) {
        const uint32_t m = m_[e];
        const uint32_t p = (e < 4) ? ((pp0 >> (8 * e)) & 0xFFu)
                                   : ((pp1 >> (8 * (e - 4))) & 0xFFu);
        const uint32_t start = hist[m >> 11] & 0x00FFFFFFu;
        scat[start + p] = ((m & 0x7FFu) << 12) | (uint32_t)(t * EPT + e);
    }
    __syncthreads();

    // ---- Phase 4 (bin-owner order): thread t resolves bins [8t, 8t+8).
    // Its scat segment and mask range are CONTIGUOUS -> near-sequential LDS/STS.
    // Every mask position is written exactly once (no pre-zeroing needed).
    {
        const uint32_t n = s_n;
        const uint4 g0 = *reinterpret_cast<const uint4*>(&hist[hb]);
        const uint4 g1 = *reinterpret_cast<const uint4*>(&hist[hb + 4]);
        const uint32_t wv[EPT] = {g0.x, g0.y, g0.z, g0.w, g1.x, g1.y, g1.z, g1.w};
#pragma unroll
        for (int e = 0; e < EPT; e++) {
            const uint32_t w = wv[e];
            const uint32_t c = w >> 24;
            const uint32_t s = w & 0x00FFFFFFu;
            for (uint32_t i = 0; i < c; i++) {
                const uint32_t ki = scat[s + i];
                uint32_t r = 0;
                for (uint32_t j = 0; j < c; j++)
                    r += (scat[s + j] < ki) ? 1u : 0u;
                mskf[s + r] = ((ki & 0xFFFu) < n) ? 1.0f : 0.0f;
            }
        }
    }
    __syncthreads();

    // ---- Phase 5: stream output (float4; mask already float)
    const float4* x4 = reinterpret_cast<const float4*>(x) + (size_t)b * (D_DIM / 4);
    float4* o4 = reinterpret_cast<float4*>(out) + (size_t)b * (2 * D_DIM / 4);
    const float4* mf4 = reinterpret_cast<const float4*>(mskf);
#pragma unroll
    for (int k = 0; k < D_DIM / 4 / TPB; k++) {
        const int i = k * TPB + t;
        const float4 mv = mf4[i];
        const float4 xv = x4[i];
        o4[i] = make_float4(xv.x * mv.x, xv.y * mv.y, xv.z * mv.z, xv.w * mv.w);
        o4[D_DIM / 4 + i] = mv;
    }
}

// ---------------- Launch ----------------

extern "C" void kernel_launch(void* const* d_in, const int* in_sizes, int n_in,
                              void* d_out, int out_size) {
    const float* x = (const float*)d_in[0];
    float* out = (float*)d_out;

    // Host-side JAX key chain (SEED = 42, threefry_partitionable fold-like split):
    //   root key K = (0, 42)
    //   k_ints = TF(K, (0,0)) ; k_perm = TF(K, (0,1))
    //   randint: (k1, k2) = split(k_ints); only k2 (lower bits) matters (span = 2^12)
    uint32_t ki0, ki1, kp0, kp1, s20, s21;
    tf2x32_host(0u, 42u, 0u, 0u, ki0, ki1);   // k_ints
    tf2x32_host(0u, 42u, 0u, 1u, kp0, kp1);   // k_perm
    tf2x32_host(ki0, ki1, 0u, 1u, s20, s21);  // second key of randint's inner split

    const int B = in_sizes[0] / D_DIM;        // 16384
    nade_mask_kernel<<<B, TPB>>>(x, out, kp0, kp1, s20, s21);
}

// round 11
// speedup vs baseline: 2.8163x; 2.8163x over previous
#include <cuda_runtime.h>
#include <cstdint>

#define D_DIM  4096
#define NBINS  8192          // top-13-bit buckets, E[occupancy] = 0.5
#define TPB    512
#define EPT    8             // elements per thread (512*8 = 4096)
#define BPT    (NBINS / TPB) // bins per thread = 16

// ---------------- Threefry-2x32 (JAX 20-round schedule), host scalar ----------------

static inline uint32_t rotl_host(uint32_t x, int r) { return (x << r) | (x >> (32 - r)); }

static void tf2x32_host(uint32_t k1, uint32_t k2, uint32_t x0, uint32_t x1,
                        uint32_t& o0, uint32_t& o1) {
    const uint32_t ks2 = k1 ^ k2 ^ 0x1BD11BDAu;
    x0 += k1; x1 += k2;
#define TF_RH(r) { x0 += x1; x1 = rotl_host(x1, (r)); x1 ^= x0; }
    TF_RH(13) TF_RH(15) TF_RH(26) TF_RH(6)   x0 += k2;  x1 += ks2 + 1u;
    TF_RH(17) TF_RH(29) TF_RH(16) TF_RH(24)  x0 += ks2; x1 += k1  + 2u;
    TF_RH(13) TF_RH(15) TF_RH(26) TF_RH(6)   x0 += k1;  x1 += k2  + 3u;
    TF_RH(17) TF_RH(29) TF_RH(16) TF_RH(24)  x0 += k2;  x1 += ks2 + 4u;
    TF_RH(13) TF_RH(15) TF_RH(26) TF_RH(6)   x0 += ks2; x1 += k1  + 5u;
#undef TF_RH
    o0 = x0; o1 = x1;
}

__device__ __forceinline__ void tf2x32_dev(uint32_t k1, uint32_t k2,
                                           uint32_t x0, uint32_t x1,
                                           uint32_t& o0, uint32_t& o1) {
    const uint32_t ks2 = k1 ^ k2 ^ 0x1BD11BDAu;
    x0 += k1; x1 += k2;
#define TF_R(r) { x0 += x1; x1 = __funnelshift_l(x1, x1, (r)); x1 ^= x0; }
    TF_R(13) TF_R(15) TF_R(26) TF_R(6)   x0 += k2;  x1 += ks2 + 1u;
    TF_R(17) TF_R(29) TF_R(16) TF_R(24)  x0 += ks2; x1 += k1  + 2u;
    TF_R(13) TF_R(15) TF_R(26) TF_R(6)   x0 += k1;  x1 += k2  + 3u;
    TF_R(17) TF_R(29) TF_R(16) TF_R(24)  x0 += k2;  x1 += ks2 + 4u;
    TF_R(13) TF_R(15) TF_R(26) TF_R(6)   x0 += ks2; x1 += k1  + 5u;
#undef TF_R
    o0 = x0; o1 = x1;
}

// ---------------- Kernel: one CTA per row ----------------
// Dynamic smem layout: hist[NBINS] | scat[D_DIM] | mskf[D_DIM]  (64 KB)

__global__ __launch_bounds__(TPB, 3)
void nade_mask_kernel(const float* __restrict__ x, float* __restrict__ out,
                      uint32_t kp0, uint32_t kp1,   // k_perm  (uniform scores)
                      uint32_t s20, uint32_t s21) { // randint lower-bits key
    extern __shared__ uint32_t smem[];
    uint32_t* hist = smem;                 // NBINS: count -> (count<<24)|excl -> cursor
    uint32_t* scat = smem + NBINS;         // D_DIM composite keys grouped by bucket
    float*    mskf = (float*)(smem + NBINS + D_DIM);  // D_DIM mask (pre-zeroed)
    __shared__ uint32_t wsum[TPB / 32];
    __shared__ uint32_t s_n;

    const int t = threadIdx.x;
    const uint32_t b = blockIdx.x;

    {   // Phase 0: vectorized zeroing of hist + mskf
        uint4 z = make_uint4(0u, 0u, 0u, 0u);
        uint4* h4 = reinterpret_cast<uint4*>(hist);
        uint4* mk4 = reinterpret_cast<uint4*>(mskf);
#pragma unroll
        for (int k = 0; k < NBINS / 4 / TPB; k++) h4[k * TPB + t] = z;
#pragma unroll
        for (int k = 0; k < D_DIM / 4 / TPB; k++) mk4[k * TPB + t] = z;
    }
    if (t == 0) {
        uint32_t o0, o1;
        tf2x32_dev(s20, s21, 0u, b, o0, o1);
        s_n = (o0 ^ o1) & (D_DIM - 1u);   // span=4096 power of two -> bits & 4095
    }
    __syncthreads();

    // ---- Phase 1: 8 threefry chains interleaved; ONE atomic pass.
    // atomicAdd return = unique within-bucket arrival index p; pack 8x8b into 2 regs.
    uint32_t m_[EPT];
    uint32_t pp0 = 0u, pp1 = 0u;
    {
        uint32_t X0[EPT], X1[EPT];
        const uint32_t ks2 = kp0 ^ kp1 ^ 0x1BD11BDAu;
        const uint32_t fbase = b * (uint32_t)D_DIM + (uint32_t)t * EPT;
#pragma unroll
        for (int e = 0; e < EPT; e++) { X0[e] = kp0; X1[e] = (fbase + (uint32_t)e) + kp1; }
#define R8(r) _Pragma("unroll") \
        for (int e = 0; e < EPT; e++) { X0[e] += X1[e]; \
            X1[e] = __funnelshift_l(X1[e], X1[e], (r)); X1[e] ^= X0[e]; }
#define INJ8(a, bb) _Pragma("unroll") \
        for (int e = 0; e < EPT; e++) { X0[e] += (a); X1[e] += (bb); }
        R8(13) R8(15) R8(26) R8(6)   INJ8(kp1, ks2 + 1u)
        R8(17) R8(29) R8(16) R8(24)  INJ8(ks2, kp0 + 2u)
        R8(13) R8(15) R8(26) R8(6)   INJ8(kp0, kp1 + 3u)
        R8(17) R8(29) R8(16) R8(24)  INJ8(kp1, ks2 + 4u)
        R8(13) R8(15) R8(26) R8(6)   INJ8(ks2, kp0 + 5u)
#undef R8
#undef INJ8
#pragma unroll
        for (int e = 0; e < EPT; e++) {
            uint32_t m = (X0[e] ^ X1[e]) >> 9;   // 23-bit mantissa key
            m_[e] = m;
            uint32_t p = atomicAdd(&hist[m >> 10], 1u);   // 13-bit bucket, arrival idx
            if (e < 4) pp0 |= p << (8 * e);
            else       pp1 |= p << (8 * (e - 4));
        }
    }
    __syncthreads();

    // ---- Phase 2: exclusive scan of 8192 bins; pack (count<<24)|excl in place.
    // loc[] eliminated (on-the-fly packing) to hold register pressure at ~R6 level.
    const int hb = t * BPT;
    uint32_t c_[BPT];
    {
        uint4* hp = reinterpret_cast<uint4*>(&hist[hb]);
#pragma unroll
        for (int q = 0; q < BPT / 4; q++) {
            uint4 hv = hp[q];
            c_[4 * q + 0] = hv.x; c_[4 * q + 1] = hv.y;
            c_[4 * q + 2] = hv.z; c_[4 * q + 3] = hv.w;
        }
    }
    uint32_t run = 0;
#pragma unroll
    for (int e = 0; e < BPT; e++) run += c_[e];
    uint32_t v = run;
    const int lane = t & 31, wid = t >> 5;
#pragma unroll
    for (int d = 1; d < 32; d <<= 1) {
        uint32_t y = __shfl_up_sync(0xFFFFFFFFu, v, d);
        if (lane >= d) v += y;
    }
    if (lane == 31) wsum[wid] = v;
    __syncthreads();
    if (t == 0) {
        uint32_t acc = 0;
#pragma unroll
        for (int i = 0; i < TPB / 32; i++) { uint32_t c = wsum[i]; wsum[i] = acc; acc += c; }
    }
    __syncthreads();
    {
        uint32_t acc = wsum[wid] + (v - run);   // thread-exclusive prefix
#pragma unroll
        for (int e = 0; e < BPT; e++) {
            uint32_t c = c_[e];
            c_[e] = (c << 24) | acc;
            acc += c;
        }
        uint4* hp = reinterpret_cast<uint4*>(&hist[hb]);
#pragma unroll
        for (int q = 0; q < BPT / 4; q++)
            hp[q] = make_uint4(c_[4 * q + 0], c_[4 * q + 1], c_[4 * q + 2], c_[4 * q + 3]);
    }
    __syncthreads();

    // ---- Phase 3: scatter composite keys into bucket segments (uniform, no branch)
#pragma unroll
    for (int e = 0; e < EPT; e++) {
        const uint32_t m = m_[e];
        const uint32_t p = (e < 4) ? ((pp0 >> (8 * e)) & 0xFFu)
                                   : ((pp1 >> (8 * (e - 4))) & 0xFFu);
        const uint32_t start = hist[m >> 10] & 0x00FFFFFFu;
        scat[start + p] = ((m & 0x3FFu) << 12) | (uint32_t)(t * EPT + e);
    }
    __syncthreads();

    // ---- Phase 4: stable rank + write 1.0f, only for idx < n.
    // idx = t*EPT+e is contiguous per warp -> the branch is warp-coherent
    // (exactly one boundary warp diverges). mskf pre-zeroed covers idx >= n.
    const uint32_t n = s_n;
#pragma unroll
    for (int e = 0; e < EPT; e++) {
        const uint32_t idx = (uint32_t)(t * EPT + e);
        if (idx < n) {
            const uint32_t m = m_[e];
            const uint32_t w = hist[m >> 10];
            const uint32_t c = w >> 24;
            const uint32_t start = w & 0x00FFFFFFu;
            uint32_t rank = start;
            if (c > 1) {
                const uint32_t packed = ((m & 0x3FFu) << 12) | idx;
                for (uint32_t q = start; q < start + c; q++)
                    rank += (scat[q] < packed) ? 1u : 0u;
            }
            mskf[rank] = 1.0f;
        }
    }
    __syncthreads();

    // ---- Phase 5: stream output (float4; mask already float)
    const float4* x4 = reinterpret_cast<const float4*>(x) + (size_t)b * (D_DIM / 4);
    float4* o4 = reinterpret_cast<float4*>(out) + (size_t)b * (2 * D_DIM / 4);
    const float4* mf4 = reinterpret_cast<const float4*>(mskf);
#pragma unroll
    for (int k = 0; k < D_DIM / 4 / TPB; k++) {
        const int i = k * TPB + t;
        const float4 mv = mf4[i];
        const float4 xv = x4[i];
        o4[i] = make_float4(xv.x * mv.x, xv.y * mv.y, xv.z * mv.z, xv.w * mv.w);
        o4[D_DIM / 4 + i] = mv;
    }
}

// ---------------- Launch ----------------

#define DYN_SMEM ((NBINS + D_DIM + D_DIM) * 4)   // 65536 bytes

extern "C" void kernel_launch(void* const* d_in, const int* in_sizes, int n_in,
                              void* d_out, int out_size) {
    const float* x = (const float*)d_in[0];
    float* out = (float*)d_out;

    static int attr_done = 0;
    if (!attr_done) {
        cudaFuncSetAttribute(nade_mask_kernel,
                             cudaFuncAttributeMaxDynamicSharedMemorySize, DYN_SMEM);
        attr_done = 1;
    }

    // Host-side JAX key chain (SEED = 42, threefry_partitionable fold-like split):
    //   root key K = (0, 42)
    //   k_ints = TF(K, (0,0)) ; k_perm = TF(K, (0,1))
    //   randint: (k1, k2) = split(k_ints); only k2 (lower bits) matters (span = 2^12)
    uint32_t ki0, ki1, kp0, kp1, s20, s21;
    tf2x32_host(0u, 42u, 0u, 0u, ki0, ki1);   // k_ints
    tf2x32_host(0u, 42u, 0u, 1u, kp0, kp1);   // k_perm
    tf2x32_host(ki0, ki1, 0u, 1u, s20, s21);  // second key of randint's inner split

    const int B = in_sizes[0] / D_DIM;        // 16384
    nade_mask_kernel<<<B, TPB, DYN_SMEM>>>(x, out, kp0, kp1, s20, s21);
}

// round 12
// speedup vs baseline: 2.8442x; 1.0099x over previous
#include <cuda_runtime.h>
#include <cstdint>

#define D_DIM 4096
#define TPB   512
#define EPT   8   // elements per thread (512*8 = 4096)

// ---------------- Threefry-2x32 (JAX 20-round schedule), host scalar ----------------

static inline uint32_t rotl_host(uint32_t x, int r) { return (x << r) | (x >> (32 - r)); }

static void tf2x32_host(uint32_t k1, uint32_t k2, uint32_t x0, uint32_t x1,
                        uint32_t& o0, uint32_t& o1) {
    const uint32_t ks2 = k1 ^ k2 ^ 0x1BD11BDAu;
    x0 += k1; x1 += k2;
#define TF_RH(r) { x0 += x1; x1 = rotl_host(x1, (r)); x1 ^= x0; }
    TF_RH(13) TF_RH(15) TF_RH(26) TF_RH(6)   x0 += k2;  x1 += ks2 + 1u;
    TF_RH(17) TF_RH(29) TF_RH(16) TF_RH(24)  x0 += ks2; x1 += k1  + 2u;
    TF_RH(13) TF_RH(15) TF_RH(26) TF_RH(6)   x0 += k1;  x1 += k2  + 3u;
    TF_RH(17) TF_RH(29) TF_RH(16) TF_RH(24)  x0 += k2;  x1 += ks2 + 4u;
    TF_RH(13) TF_RH(15) TF_RH(26) TF_RH(6)   x0 += ks2; x1 += k1  + 5u;
#undef TF_RH
    o0 = x0; o1 = x1;
}

// Device scalar version (used once per block for the randint draw)
__device__ __forceinline__ void tf2x32_dev(uint32_t k1, uint32_t k2,
                                           uint32_t x0, uint32_t x1,
                                           uint32_t& o0, uint32_t& o1) {
    const uint32_t ks2 = k1 ^ k2 ^ 0x1BD11BDAu;
    x0 += k1; x1 += k2;
#define TF_R(r) { x0 += x1; x1 = __funnelshift_l(x1, x1, (r)); x1 ^= x0; }
    TF_R(13) TF_R(15) TF_R(26) TF_R(6)   x0 += k2;  x1 += ks2 + 1u;
    TF_R(17) TF_R(29) TF_R(16) TF_R(24)  x0 += ks2; x1 += k1  + 2u;
    TF_R(13) TF_R(15) TF_R(26) TF_R(6)   x0 += k1;  x1 += k2  + 3u;
    TF_R(17) TF_R(29) TF_R(16) TF_R(24)  x0 += k2;  x1 += ks2 + 4u;
    TF_R(13) TF_R(15) TF_R(26) TF_R(6)   x0 += ks2; x1 += k1  + 5u;
#undef TF_R
    o0 = x0; o1 = x1;
}

// Add forced onto the FMA pipe: mad.lo.u32 with an opaque runtime "one".
// ptxas cannot strength-reduce (one is a register of unknown value) -> IMAD.
__device__ __forceinline__ uint32_t madd(uint32_t a, uint32_t one, uint32_t c) {
    uint32_t r;
    asm("mad.lo.u32 %0, %1, %2, %3;" : "=r"(r) : "r"(a), "r"(one), "r"(c));
    return r;
}

// ---------------- Kernel: one CTA per row ----------------

__global__ __launch_bounds__(TPB, 3)
void nade_mask_kernel(const float* __restrict__ x, float* __restrict__ out,
                      uint32_t kp0, uint32_t kp1,   // k_perm  (uniform scores)
                      uint32_t s20, uint32_t s21,   // randint lower-bits key
                      uint32_t one) {               // == 1 (opaque to ptxas)
    __shared__ uint32_t hist[D_DIM];     // count -> (count<<24)|excl_prefix
    __shared__ uint32_t scat[D_DIM];     // composite keys grouped by bucket
    __shared__ float    mskf[D_DIM];     // final per-position mask (fully written in P4)
    __shared__ uint32_t wsum[TPB / 32];
    __shared__ uint32_t s_n;

    const int t = threadIdx.x;
    const uint32_t b = blockIdx.x;

    {   // vectorized zeroing of hist
        uint4 z = make_uint4(0u, 0u, 0u, 0u);
        uint4* h4 = reinterpret_cast<uint4*>(hist);
#pragma unroll
        for (int k = 0; k < D_DIM / 4 / TPB; k++) h4[k * TPB + t] = z;
    }
    if (t == 0) {
        uint32_t o0, o1;
        tf2x32_dev(s20, s21, 0u, b, o0, o1);
        s_n = (o0 ^ o1) & (D_DIM - 1u);   // span=4096 power of two -> bits & 4095
    }
    __syncthreads();

    // ---- Phase 1: 8 threefry chains interleaved; adds forced to FMA pipe (IMAD),
    // SHF/LOP3 stay on alu pipe -> ~balanced integer throughput across both pipes.
    uint32_t m_[EPT];
    uint32_t pp0 = 0u, pp1 = 0u;
    {
        uint32_t X0[EPT], X1[EPT];
        const uint32_t ks2 = kp0 ^ kp1 ^ 0x1BD11BDAu;
        const uint32_t fbase = b * (uint32_t)D_DIM + (uint32_t)t * EPT;
#pragma unroll
        for (int e = 0; e < EPT; e++) { X0[e] = kp0; X1[e] = (fbase + (uint32_t)e) + kp1; }
#define R8(r) _Pragma("unroll") \
        for (int e = 0; e < EPT; e++) { X0[e] = madd(X1[e], one, X0[e]); \
            X1[e] = __funnelshift_l(X1[e], X1[e], (r)); X1[e] ^= X0[e]; }
#define INJ8(a, bb) _Pragma("unroll") \
        for (int e = 0; e < EPT; e++) { X0[e] = madd((a), one, X0[e]); \
            X1[e] = madd((bb), one, X1[e]); }
        R8(13) R8(15) R8(26) R8(6)   INJ8(kp1, ks2 + 1u)
        R8(17) R8(29) R8(16) R8(24)  INJ8(ks2, kp0 + 2u)
        R8(13) R8(15) R8(26) R8(6)   INJ8(kp0, kp1 + 3u)
        R8(17) R8(29) R8(16) R8(24)  INJ8(kp1, ks2 + 4u)
        R8(13) R8(15) R8(26) R8(6)   INJ8(ks2, kp0 + 5u)
#undef R8
#undef INJ8
#pragma unroll
        for (int e = 0; e < EPT; e++) {
            uint32_t m = (X0[e] ^ X1[e]) >> 9;   // 23-bit mantissa key
            m_[e] = m;
            uint32_t p = atomicAdd(&hist[m >> 11], 1u);   // arrival index
            if (e < 4) pp0 |= p << (8 * e);
            else       pp1 |= p << (8 * (e - 4));
        }
    }
    __syncthreads();

    // ---- Phase 2: exclusive scan of 4096 bins; pack (count<<24)|excl back into hist
    const int hb = t * EPT;
    uint4 h0 = *reinterpret_cast<uint4*>(&hist[hb]);
    uint4 h1 = *reinterpret_cast<uint4*>(&hist[hb + 4]);
    uint32_t c_[EPT] = {h0.x, h0.y, h0.z, h0.w, h1.x, h1.y, h1.z, h1.w};
    uint32_t loc[EPT], run = 0;
#pragma unroll
    for (int e = 0; e < EPT; e++) { loc[e] = run; run += c_[e]; }
    uint32_t v = run;
    const int lane = t & 31, wid = t >> 5;
#pragma unroll
    for (int d = 1; d < 32; d <<= 1) {
        uint32_t y = __shfl_up_sync(0xFFFFFFFFu, v, d);
        if (lane >= d) v += y;
    }
    if (lane == 31) wsum[wid] = v;
    __syncthreads();
    if (t == 0) {
        uint32_t acc = 0;
#pragma unroll
        for (int i = 0; i < TPB / 32; i++) { uint32_t c = wsum[i]; wsum[i] = acc; acc += c; }
    }
    __syncthreads();
    const uint32_t texcl = wsum[wid] + (v - run);
    h0.x = (c_[0] << 24) | (texcl + loc[0]);
    h0.y = (c_[1] << 24) | (texcl + loc[1]);
    h0.z = (c_[2] << 24) | (texcl + loc[2]);
    h0.w = (c_[3] << 24) | (texcl + loc[3]);
    h1.x = (c_[4] << 24) | (texcl + loc[4]);
    h1.y = (c_[5] << 24) | (texcl + loc[5]);
    h1.z = (c_[6] << 24) | (texcl + loc[6]);
    h1.w = (c_[7] << 24) | (texcl + loc[7]);
    *reinterpret_cast<uint4*>(&hist[hb]) = h0;
    *reinterpret_cast<uint4*>(&hist[hb + 4]) = h1;
    __syncthreads();

    // ---- Phase 3: scatter composite keys into bucket segments (uniform, no branch)
#pragma unroll
    for (int e = 0; e < EPT; e++) {
        const uint32_t m = m_[e];
        const uint32_t p = (e < 4) ? ((pp0 >> (8 * e)) & 0xFFu)
                                   : ((pp1 >> (8 * (e - 4))) & 0xFFu);
        const uint32_t start = hist[m >> 11] & 0x00FFFFFFu;
        scat[start + p] = ((m & 0x7FFu) << 12) | (uint32_t)(t * EPT + e);
    }
    __syncthreads();

    // ---- Phase 4: within-bucket stable rank + float mask write (uniform)
    const uint32_t n = s_n;
#pragma unroll
    for (int e = 0; e < EPT; e++) {
        const uint32_t idx = (uint32_t)(t * EPT + e);
        const uint32_t m = m_[e];
        const uint32_t w = hist[m >> 11];
        const uint32_t c = w >> 24;
        const uint32_t start = w & 0x00FFFFFFu;
        uint32_t rank = start;
        if (c > 1) {
            const uint32_t packed = ((m & 0x7FFu) << 12) | idx;
            for (uint32_t q = start; q < start + c; q++)
                rank += (scat[q] < packed) ? 1u : 0u;
        }
        mskf[rank] = (idx < n) ? 1.0f : 0.0f;
    }
    __syncthreads();

    // ---- Phase 5: stream output (float4; mask already float)
    const float4* x4 = reinterpret_cast<const float4*>(x) + (size_t)b * (D_DIM / 4);
    float4* o4 = reinterpret_cast<float4*>(out) + (size_t)b * (2 * D_DIM / 4);
    const float4* mf4 = reinterpret_cast<const float4*>(mskf);
#pragma unroll
    for (int k = 0; k < D_DIM / 4 / TPB; k++) {
        const int i = k * TPB + t;
        const float4 mv = mf4[i];
        const float4 xv = x4[i];
        o4[i] = make_float4(xv.x * mv.x, xv.y * mv.y, xv.z * mv.z, xv.w * mv.w);
        o4[D_DIM / 4 + i] = mv;
    }
}

// ---------------- Launch ----------------

extern "C" void kernel_launch(void* const* d_in, const int* in_sizes, int n_in,
                              void* d_out, int out_size) {
    const float* x = (const float*)d_in[0];
    float* out = (float*)d_out;

    // Host-side JAX key chain (SEED = 42, threefry_partitionable fold-like split):
    //   root key K = (0, 42)
    //   k_ints = TF(K, (0,0)) ; k_perm = TF(K, (0,1))
    //   randint: (k1, k2) = split(k_ints); only k2 (lower bits) matters (span = 2^12)
    uint32_t ki0, ki1, kp0, kp1, s20, s21;
    tf2x32_host(0u, 42u, 0u, 0u, ki0, ki1);   // k_ints
    tf2x32_host(0u, 42u, 0u, 1u, kp0, kp1);   // k_perm
    tf2x32_host(ki0, ki1, 0u, 1u, s20, s21);  // second key of randint's inner split

    const int B = in_sizes[0] / D_DIM;        // 16384
    nade_mask_kernel<<<B, TPB>>>(x, out, kp0, kp1, s20, s21, 1u);
}

// round 13
// speedup vs baseline: 3.1322x; 1.1012x over previous
#include <cuda_runtime.h>
#include <cstdint>

#define D_DIM 4096
#define TPB   512
#define EPT   8   // elements per thread (512*8 = 4096)
#define HALF  4   // threefry chains interleaved per pass (2 passes)

// ---------------- Threefry-2x32 (JAX 20-round schedule), host scalar ----------------

static inline uint32_t rotl_host(uint32_t x, int r) { return (x << r) | (x >> (32 - r)); }

static void tf2x32_host(uint32_t k1, uint32_t k2, uint32_t x0, uint32_t x1,
                        uint32_t& o0, uint32_t& o1) {
    const uint32_t ks2 = k1 ^ k2 ^ 0x1BD11BDAu;
    x0 += k1; x1 += k2;
#define TF_RH(r) { x0 += x1; x1 = rotl_host(x1, (r)); x1 ^= x0; }
    TF_RH(13) TF_RH(15) TF_RH(26) TF_RH(6)   x0 += k2;  x1 += ks2 + 1u;
    TF_RH(17) TF_RH(29) TF_RH(16) TF_RH(24)  x0 += ks2; x1 += k1  + 2u;
    TF_RH(13) TF_RH(15) TF_RH(26) TF_RH(6)   x0 += k1;  x1 += k2  + 3u;
    TF_RH(17) TF_RH(29) TF_RH(16) TF_RH(24)  x0 += k2;  x1 += ks2 + 4u;
    TF_RH(13) TF_RH(15) TF_RH(26) TF_RH(6)   x0 += ks2; x1 += k1  + 5u;
#undef TF_RH
    o0 = x0; o1 = x1;
}

// Device scalar version (used once per block for the randint draw)
__device__ __forceinline__ void tf2x32_dev(uint32_t k1, uint32_t k2,
                                           uint32_t x0, uint32_t x1,
                                           uint32_t& o0, uint32_t& o1) {
    const uint32_t ks2 = k1 ^ k2 ^ 0x1BD11BDAu;
    x0 += k1; x1 += k2;
#define TF_R(r) { x0 += x1; x1 = __funnelshift_l(x1, x1, (r)); x1 ^= x0; }
    TF_R(13) TF_R(15) TF_R(26) TF_R(6)   x0 += k2;  x1 += ks2 + 1u;
    TF_R(17) TF_R(29) TF_R(16) TF_R(24)  x0 += ks2; x1 += k1  + 2u;
    TF_R(13) TF_R(15) TF_R(26) TF_R(6)   x0 += k1;  x1 += k2  + 3u;
    TF_R(17) TF_R(29) TF_R(16) TF_R(24)  x0 += k2;  x1 += ks2 + 4u;
    TF_R(13) TF_R(15) TF_R(26) TF_R(6)   x0 += ks2; x1 += k1  + 5u;
#undef TF_R
    o0 = x0; o1 = x1;
}

// ---------------- Kernel: one CTA per row ----------------
// __launch_bounds__(512, 4): cap regs at 32 -> 4 CTAs/SM -> 64 warps (full occ).
// Phase 1 runs 2 passes of 4 interleaved chains to fit the 32-reg budget.

__global__ __launch_bounds__(TPB, 4)
void nade_mask_kernel(const float* __restrict__ x, float* __restrict__ out,
                      uint32_t kp0, uint32_t kp1,   // k_perm  (uniform scores)
                      uint32_t s20, uint32_t s21) { // randint lower-bits key
    __shared__ uint32_t hist[D_DIM];     // count -> (count<<24)|excl_prefix
    __shared__ uint32_t scat[D_DIM];     // composite keys grouped by bucket
    __shared__ float    mskf[D_DIM];     // final per-position mask (fully written in P4)
    __shared__ uint32_t wsum[TPB / 32];
    __shared__ uint32_t s_n;

    const int t = threadIdx.x;
    const uint32_t b = blockIdx.x;

    {   // vectorized zeroing of hist
        uint4 z = make_uint4(0u, 0u, 0u, 0u);
        uint4* h4 = reinterpret_cast<uint4*>(hist);
#pragma unroll
        for (int k = 0; k < D_DIM / 4 / TPB; k++) h4[k * TPB + t] = z;
    }
    if (t == 0) {
        uint32_t o0, o1;
        tf2x32_dev(s20, s21, 0u, b, o0, o1);
        s_n = (o0 ^ o1) & (D_DIM - 1u);   // span=4096 power of two -> bits & 4095
    }
    __syncthreads();

    // ---- Phase 1: threefry in 2 passes of 4 interleaved chains (reg diet);
    // one atomic pass; atomicAdd return = within-bucket arrival index p.
    uint32_t m_[EPT];
    uint32_t pp0 = 0u, pp1 = 0u;
    {
        const uint32_t ks2 = kp0 ^ kp1 ^ 0x1BD11BDAu;
        const uint32_t fbase = b * (uint32_t)D_DIM + (uint32_t)t * EPT;
#pragma unroll
        for (int pass = 0; pass < 2; pass++) {
            uint32_t X0[HALF], X1[HALF];
#pragma unroll
            for (int e = 0; e < HALF; e++) {
                X0[e] = kp0;
                X1[e] = (fbase + (uint32_t)(pass * HALF + e)) + kp1;
            }
#define R4(r) _Pragma("unroll") \
            for (int e = 0; e < HALF; e++) { X0[e] += X1[e]; \
                X1[e] = __funnelshift_l(X1[e], X1[e], (r)); X1[e] ^= X0[e]; }
#define INJ4(a, bb) _Pragma("unroll") \
            for (int e = 0; e < HALF; e++) { X0[e] += (a); X1[e] += (bb); }
            R4(13) R4(15) R4(26) R4(6)   INJ4(kp1, ks2 + 1u)
            R4(17) R4(29) R4(16) R4(24)  INJ4(ks2, kp0 + 2u)
            R4(13) R4(15) R4(26) R4(6)   INJ4(kp0, kp1 + 3u)
            R4(17) R4(29) R4(16) R4(24)  INJ4(kp1, ks2 + 4u)
            R4(13) R4(15) R4(26) R4(6)   INJ4(ks2, kp0 + 5u)
#undef R4
#undef INJ4
#pragma unroll
            for (int e = 0; e < HALF; e++) {
                uint32_t m = (X0[e] ^ X1[e]) >> 9;   // 23-bit mantissa key
                m_[pass * HALF + e] = m;
                uint32_t p = atomicAdd(&hist[m >> 11], 1u);   // arrival index
                if (pass == 0) pp0 |= p << (8 * e);
                else           pp1 |= p << (8 * e);
            }
        }
    }
    __syncthreads();

    // ---- Phase 2: exclusive scan of 4096 bins; pack (count<<24)|excl back into hist
    const int hb = t * EPT;
    uint4 h0 = *reinterpret_cast<uint4*>(&hist[hb]);
    uint4 h1 = *reinterpret_cast<uint4*>(&hist[hb + 4]);
    uint32_t c_[EPT] = {h0.x, h0.y, h0.z, h0.w, h1.x, h1.y, h1.z, h1.w};
    uint32_t run = 0;
#pragma unroll
    for (int e = 0; e < EPT; e++) run += c_[e];
    uint32_t v = run;
    const int lane = t & 31, wid = t >> 5;
#pragma unroll
    for (int d = 1; d < 32; d <<= 1) {
        uint32_t y = __shfl_up_sync(0xFFFFFFFFu, v, d);
        if (lane >= d) v += y;
    }
    if (lane == 31) wsum[wid] = v;
    __syncthreads();
    if (t == 0) {
        uint32_t acc = 0;
#pragma unroll
        for (int i = 0; i < TPB / 32; i++) { uint32_t c = wsum[i]; wsum[i] = acc; acc += c; }
    }
    __syncthreads();
    {
        uint32_t acc = wsum[wid] + (v - run);   // thread-exclusive prefix (on-the-fly pack)
#pragma unroll
        for (int e = 0; e < EPT; e++) {
            uint32_t c = c_[e];
            c_[e] = (c << 24) | acc;
            acc += c;
        }
        h0 = make_uint4(c_[0], c_[1], c_[2], c_[3]);
        h1 = make_uint4(c_[4], c_[5], c_[6], c_[7]);
        *reinterpret_cast<uint4*>(&hist[hb]) = h0;
        *reinterpret_cast<uint4*>(&hist[hb + 4]) = h1;
    }
    __syncthreads();

    // ---- Phase 3: scatter composite keys into bucket segments (uniform, no branch)
#pragma unroll
    for (int e = 0; e < EPT; e++) {
        const uint32_t m = m_[e];
        const uint32_t p = (e < 4) ? ((pp0 >> (8 * e)) & 0xFFu)
                                   : ((pp1 >> (8 * (e - 4))) & 0xFFu);
        const uint32_t start = hist[m >> 11] & 0x00FFFFFFu;
        scat[start + p] = ((m & 0x7FFu) << 12) | (uint32_t)(t * EPT + e);
    }
    __syncthreads();

    // ---- Phase 4: within-bucket stable rank + float mask write (uniform, branchless)
    const uint32_t n = s_n;
#pragma unroll
    for (int e = 0; e < EPT; e++) {
        const uint32_t idx = (uint32_t)(t * EPT + e);
        const uint32_t m = m_[e];
        const uint32_t w = hist[m >> 11];
        const uint32_t c = w >> 24;
        const uint32_t start = w & 0x00FFFFFFu;
        const uint32_t packed = ((m & 0x7FFu) << 12) | idx;
        uint32_t rank = start;
        for (uint32_t q = start; q < start + c; q++)
            rank += (scat[q] < packed) ? 1u : 0u;   // self-compare contributes 0
        mskf[rank] = (idx < n) ? 1.0f : 0.0f;
    }
    __syncthreads();

    // ---- Phase 5: stream output (float4; mask already float)
    const float4* x4 = reinterpret_cast<const float4*>(x) + (size_t)b * (D_DIM / 4);
    float4* o4 = reinterpret_cast<float4*>(out) + (size_t)b * (2 * D_DIM / 4);
    const float4* mf4 = reinterpret_cast<const float4*>(mskf);
#pragma unroll
    for (int k = 0; k < D_DIM / 4 / TPB; k++) {
        const int i = k * TPB + t;
        const float4 mv = mf4[i];
        const float4 xv = x4[i];
        o4[i] = make_float4(xv.x * mv.x, xv.y * mv.y, xv.z * mv.z, xv.w * mv.w);
        o4[D_DIM / 4 + i] = mv;
    }
}

// ---------------- Launch ----------------

extern "C" void kernel_launch(void* const* d_in, const int* in_sizes, int n_in,
                              void* d_out, int out_size) {
    const float* x = (const float*)d_in[0];
    float* out = (float*)d_out;

    // Host-side JAX key chain (SEED = 42, threefry_partitionable fold-like split):
    //   root key K = (0, 42)
    //   k_ints = TF(K, (0,0)) ; k_perm = TF(K, (0,1))
    //   randint: (k1, k2) = split(k_ints); only k2 (lower bits) matters (span = 2^12)
    uint32_t ki0, ki1, kp0, kp1, s20, s21;
    tf2x32_host(0u, 42u, 0u, 0u, ki0, ki1);   // k_ints
    tf2x32_host(0u, 42u, 0u, 1u, kp0, kp1);   // k_perm
    tf2x32_host(ki0, ki1, 0u, 1u, s20, s21);  // second key of randint's inner split

    const int B = in_sizes[0] / D_DIM;        // 16384
    nade_mask_kernel<<<B, TPB>>>(x, out, kp0, kp1, s20, s21);
}